// round 8
// baseline (speedup 1.0000x reference)
#include <cuda_runtime.h>
#include <cuda_fp16.h>
#include <cstdint>
#include <math.h>

#define BB   64
#define CIN  256
#define HID  256
#define TT   512
#define G4   1024   // 4*HID

// ---------------- scratch (__device__ globals) ------------------------------
__device__ float g_wx[(size_t)TT * BB * G4];      // [t][b][col]  128 MiB
__device__ uint4 g_wA[(size_t)BB * 2 * 16 * 512]; // own-k block
__device__ uint4 g_wB[(size_t)BB * 2 * 16 * 512]; // peer-k block

// column slot lc in [0,512) -> global gate column.
// tid<128 -> gates (i=0, g=2) of unit tid; tid>=128 -> gates (f=1, o=3)
__device__ __forceinline__ int gcol(int lc, int half) {
    int th  = lc & 255;
    int sel = lc >> 8;
    int g   = (th < 128) ? (sel * 2) : (sel * 2 + 1);
    int j   = th & 127;
    return g * 256 + half * 128 + j;
}

__device__ __forceinline__ float tanh_f(float x) {
    float e = __expf(2.0f * x);
    return 1.0f - __fdividef(2.0f, e + 1.0f);
}
__device__ __forceinline__ float sig_f(float x) {
    return __fdividef(1.0f, 1.0f + __expf(-x));
}

// ---------------- conv: W_hh fp32 -> fp16 blobs ------------------------------
__global__ __launch_bounds__(256) void conv_whh_kernel(const float* __restrict__ Whh) {
    int t    = blockIdx.x * 256 + threadIdx.x;
    int lc   = t & 511;
    int k8   = (t >> 9) & 15;
    int half = (t >> 13) & 1;
    int b    = t >> 14;
    int col  = gcol(lc, half);
    {
        int kg0 = half * 128 + k8 * 8;
        const float* s = Whh + ((size_t)b * HID + kg0) * G4 + col;
        __half hx[8];
        #pragma unroll
        for (int i = 0; i < 8; i++) hx[i] = __float2half(s[(size_t)i * G4]);
        g_wA[t] = *(uint4*)hx;
    }
    {
        int kg0 = (1 - half) * 128 + k8 * 8;
        const float* s = Whh + ((size_t)b * HID + kg0) * G4 + col;
        __half hx[8];
        #pragma unroll
        for (int i = 0; i < 8; i++) hx[i] = __float2half(s[(size_t)i * G4]);
        g_wB[t] = *(uint4*)hx;
    }
}

// ---------------- phase 1: single-kernel HMMA GEMM (proven) -----------------
__device__ __forceinline__ void mma16816(float* d, const uint32_t* a, const uint32_t* bf) {
    asm volatile(
        "mma.sync.aligned.m16n8k16.row.col.f32.f16.f16.f32 "
        "{%0,%1,%2,%3}, {%4,%5,%6,%7}, {%8,%9}, {%0,%1,%2,%3};"
        : "+f"(d[0]), "+f"(d[1]), "+f"(d[2]), "+f"(d[3])
        : "r"(a[0]), "r"(a[1]), "r"(a[2]), "r"(a[3]), "r"(bf[0]), "r"(bf[1]));
}

#define LDA 40

__global__ __launch_bounds__(256) void wx_hmma_kernel(
    const float* __restrict__ x,
    const float* __restrict__ Wih,
    const float* __restrict__ bh)
{
    __shared__ __half As[128 * LDA];
    __shared__ __half Bs[128 * LDA];

    const int tid  = threadIdx.x;
    const int m0   = blockIdx.x * 128;
    const int n0   = blockIdx.y * 128;
    const int b    = blockIdx.z;
    const int wid  = tid >> 5, lane = tid & 31;
    const int wm   = (wid & 1) * 64, wn = (wid >> 1) * 32;
    const int g    = lane >> 2, tig = lane & 3;

    float acc[4][4][4];
    #pragma unroll
    for (int i = 0; i < 4; i++)
        #pragma unroll
        for (int j = 0; j < 4; j++)
            #pragma unroll
            for (int r = 0; r < 4; r++) acc[i][j][r] = 0.0f;

    const float* xb = x   + (size_t)b * CIN * TT + m0;
    const float* wb = Wih + (size_t)b * CIN * G4 + n0;

    #pragma unroll 1
    for (int kb = 0; kb < CIN; kb += 32) {
        #pragma unroll
        for (int i = 0; i < 4; i++) {
            int idx = tid + i * 256;
            int kl = idx >> 5, tq = idx & 31;
            float4 v = *(const float4*)(xb + (size_t)(kb + kl) * TT + tq * 4);
            __half* d = As + (tq * 4) * LDA + kl;
            d[0]       = __float2half_rn(v.x);
            d[LDA]     = __float2half_rn(v.y);
            d[2 * LDA] = __float2half_rn(v.z);
            d[3 * LDA] = __float2half_rn(v.w);
        }
        #pragma unroll
        for (int i = 0; i < 4; i++) {
            int idx = tid + i * 256;
            int kl = idx >> 5, nq = idx & 31;
            float4 v = *(const float4*)(wb + (size_t)(kb + kl) * G4 + nq * 4);
            __half* d = Bs + (nq * 4) * LDA + kl;
            d[0]       = __float2half_rn(v.x);
            d[LDA]     = __float2half_rn(v.y);
            d[2 * LDA] = __float2half_rn(v.z);
            d[3 * LDA] = __float2half_rn(v.w);
        }
        __syncthreads();

        #pragma unroll
        for (int ks = 0; ks < 2; ks++) {
            uint32_t a[4][4], bf[4][2];
            #pragma unroll
            for (int mf = 0; mf < 4; mf++) {
                const __half* base = As + (wm + mf * 16 + g) * LDA + ks * 16 + tig * 2;
                a[mf][0] = *(const uint32_t*)(base);
                a[mf][1] = *(const uint32_t*)(base + 8 * LDA);
                a[mf][2] = *(const uint32_t*)(base + 8);
                a[mf][3] = *(const uint32_t*)(base + 8 * LDA + 8);
            }
            #pragma unroll
            for (int nf = 0; nf < 4; nf++) {
                const __half* base = Bs + (wn + nf * 8 + g) * LDA + ks * 16 + tig * 2;
                bf[nf][0] = *(const uint32_t*)(base);
                bf[nf][1] = *(const uint32_t*)(base + 8);
            }
            #pragma unroll
            for (int mf = 0; mf < 4; mf++)
                #pragma unroll
                for (int nf = 0; nf < 4; nf++)
                    mma16816(acc[mf][nf], a[mf], bf[nf]);
        }
        __syncthreads();
    }

    #pragma unroll
    for (int nf = 0; nf < 4; nf++) {
        int col = n0 + wn + nf * 8 + tig * 2;
        float2 bias = *(const float2*)(bh + (size_t)b * G4 + col);
        #pragma unroll
        for (int mf = 0; mf < 4; mf++) {
            int t0 = m0 + wm + mf * 16 + g;
            float2 v0 = { acc[mf][nf][0] + bias.x, acc[mf][nf][1] + bias.y };
            float2 v1 = { acc[mf][nf][2] + bias.x, acc[mf][nf][3] + bias.y };
            *(float2*)(g_wx + ((size_t)t0 * BB + b) * G4 + col) = v0;
            *(float2*)(g_wx + ((size_t)(t0 + 8) * BB + b) * G4 + col) = v1;
        }
    }
}

// ---------------- phase 2: recurrence, mbarrier h-exchange ------------------
#define SMEM_W_BYTES  (8 * 512 * 16)                  // 65536
#define SMEM_HS_OFF   SMEM_W_BYTES
#define SMEM_GS_OFF   (SMEM_HS_OFF + 2 * 128 * 4)
#define SMEM_MB_OFF   (SMEM_GS_OFF + 128 * 4)         // 2 mbarriers
#define SMEM_TOTAL_R  (SMEM_MB_OFF + 16)              // 67088 B

__device__ __forceinline__ void mbar_wait_acq_cluster(uint32_t addr, uint32_t parity) {
    asm volatile(
        "{\n\t.reg .pred P;\n\t"
        "W_%=:\n\t"
        "mbarrier.try_wait.parity.acquire.cluster.shared::cta.b64 P, [%0], %1;\n\t"
        "@P bra.uni D_%=;\n\t"
        "bra.uni W_%=;\n\t"
        "D_%=:\n\t}"
        :: "r"(addr), "r"(parity) : "memory");
}

__global__ void __cluster_dims__(2, 1, 1) __launch_bounds__(256, 1)
lstm_rec_kernel(const float* __restrict__ h0,
                const float* __restrict__ c0,
                float* __restrict__ out)
{
    extern __shared__ char smem[];
    uint4*   w_s  = (uint4*)smem;                     // peer chunks 8..15
    __half2* hs2  = (__half2*)(smem + SMEM_HS_OFF);
    float*   gsh  = (float*)(smem + SMEM_GS_OFF);

    const int tid    = threadIdx.x;
    const int b      = blockIdx.x >> 1;
    const int half   = blockIdx.x & 1;
    const int HALF16 = half * 16;
    const int PEER16 = 16 - HALF16;
    const bool hi    = (tid >= 128);
    const int  j     = tid & 127;

    // weight residency
    uint4 wregA[16], wregB[16], wregPA[8], wregPB[8];
    const uint4* gwa = g_wA + ((size_t)(b * 2 + half) << 13);
    #pragma unroll
    for (int a = 0; a < 16; a++) {
        wregA[a] = gwa[a * 512 + tid];
        wregB[a] = gwa[a * 512 + tid + 256];
    }
    const uint4* gwb = g_wB + ((size_t)(b * 2 + half) << 13);
    #pragma unroll
    for (int a = 0; a < 8; a++) {
        wregPA[a] = gwb[a * 512 + tid];
        wregPB[a] = gwb[a * 512 + tid + 256];
    }
    #pragma unroll
    for (int a = 8; a < 16; a++) {
        w_s[(a - 8) * 512 + tid]       = gwb[a * 512 + tid];
        w_s[(a - 8) * 512 + tid + 256] = gwb[a * 512 + tid + 256];
    }

    const uint32_t smemBase   = (uint32_t)__cvta_generic_to_shared(smem);
    const uint32_t hsAddrBase = smemBase + SMEM_HS_OFF;
    const uint32_t mbarBase   = smemBase + SMEM_MB_OFF;
    const uint32_t peerRank   = (uint32_t)(half ^ 1);

    // init mbarriers (64 producer arrivals each)
    if (tid == 0) {
        asm volatile("mbarrier.init.shared.b64 [%0], 64;" :: "r"(mbarBase)     : "memory");
        asm volatile("mbarrier.init.shared.b64 [%0], 64;" :: "r"(mbarBase + 8) : "memory");
    }

    // init state
    float c = 0.0f;
    if (hi) c = c0[b * HID + half * 128 + j];
    if (tid < 128)
        hs2[tid] = __floats2half2_rn(h0[b * HID + 2 * tid],
                                     h0[b * HID + 2 * tid + 1]);
    __syncthreads();
    asm volatile("barrier.cluster.arrive.aligned;\n\t"
                 "barrier.cluster.wait.aligned;" ::: "memory");

    // precompute remote addresses (mapa is loop-invariant)
    uint32_t rHsBase, rMbar0, rMbar1;
    asm volatile("mapa.shared::cluster.u32 %0, %1, %2;"
                 : "=r"(rHsBase) : "r"(hsAddrBase), "r"(peerRank));
    asm volatile("mapa.shared::cluster.u32 %0, %1, %2;"
                 : "=r"(rMbar0) : "r"(mbarBase), "r"(peerRank));
    asm volatile("mapa.shared::cluster.u32 %0, %1, %2;"
                 : "=r"(rMbar1) : "r"(mbarBase + 8), "r"(peerRank));

    const int colA = gcol(tid, half);
    const float* wxA_ptr = g_wx + (size_t)b * G4 + colA;
    const float* wxB_ptr = wxA_ptr + 512;

    float wxA = __ldg(wxA_ptr);
    float wxB = __ldg(wxB_ptr);
    const __half2 hz = __float2half2_rn(0.0f);

    uint32_t par0 = 0, par1 = 0;   // consumer parity trackers

    #pragma unroll 1
    for (int t = 0; t < TT; t++) {
        const int p = t & 1;

        float nxA = wxA, nxB = wxB;
        if (t + 1 < TT) {
            size_t off = (size_t)(t + 1) * (BB * G4);
            nxA = __ldg(wxA_ptr + off);
            nxB = __ldg(wxB_ptr + off);
        }

        float accA = wxA, accB = wxB;
        const __half2* hsp = hs2 + p * 128;

        // ---- phase A: own-k block (register weights, local h) ----
        #pragma unroll
        for (int q = 0; q < 4; q++) {
            __half2 sA = hz, sB = hz;
            #pragma unroll
            for (int i = 0; i < 4; i++) {
                int a  = q * 4 + i;
                int k8 = HALF16 + a;
                uint4 hv = *(const uint4*)(hsp + k8 * 4);
                __half2 h01 = *(__half2*)&hv.x, h23 = *(__half2*)&hv.y;
                __half2 h45 = *(__half2*)&hv.z, h67 = *(__half2*)&hv.w;
                uint4 wa = wregA[a], wb = wregB[a];
                sA = __hfma2(h01, *(__half2*)&wa.x, sA);
                sA = __hfma2(h23, *(__half2*)&wa.y, sA);
                sA = __hfma2(h45, *(__half2*)&wa.z, sA);
                sA = __hfma2(h67, *(__half2*)&wa.w, sA);
                sB = __hfma2(h01, *(__half2*)&wb.x, sB);
                sB = __hfma2(h23, *(__half2*)&wb.y, sB);
                sB = __hfma2(h45, *(__half2*)&wb.z, sB);
                sB = __hfma2(h67, *(__half2*)&wb.w, sB);
            }
            float2 fa = __half22float2(sA); accA += fa.x + fa.y;
            float2 fb = __half22float2(sB); accB += fb.x + fb.y;
        }

        // ---- wait for peer h of this step (mbarrier, fast path) ----
        if (t) {
            if (t & 1) { mbar_wait_acq_cluster(mbarBase + 8, par1); par1 ^= 1; }
            else       { mbar_wait_acq_cluster(mbarBase,     par0); par0 ^= 1; }
        }

        // ---- phase B: peer-k block (8 reg chunks + 8 SMEM chunks) ----
        #pragma unroll
        for (int q = 0; q < 4; q++) {
            __half2 sA = hz, sB = hz;
            #pragma unroll
            for (int i = 0; i < 4; i++) {
                int bi = q * 4 + i;
                int k8 = PEER16 + bi;
                uint4 hv = *(const uint4*)(hsp + k8 * 4);
                __half2 h01 = *(__half2*)&hv.x, h23 = *(__half2*)&hv.y;
                __half2 h45 = *(__half2*)&hv.z, h67 = *(__half2*)&hv.w;
                uint4 wa, wb;
                if (bi < 8) { wa = wregPA[bi]; wb = wregPB[bi]; }
                else {
                    wa = w_s[(bi - 8) * 512 + tid];
                    wb = w_s[(bi - 8) * 512 + tid + 256];
                }
                sA = __hfma2(h01, *(__half2*)&wa.x, sA);
                sA = __hfma2(h23, *(__half2*)&wa.y, sA);
                sA = __hfma2(h45, *(__half2*)&wa.z, sA);
                sA = __hfma2(h67, *(__half2*)&wa.w, sA);
                sB = __hfma2(h01, *(__half2*)&wb.x, sB);
                sB = __hfma2(h23, *(__half2*)&wb.y, sB);
                sB = __hfma2(h45, *(__half2*)&wb.z, sB);
                sB = __hfma2(h67, *(__half2*)&wb.w, sB);
            }
            float2 fa = __half22float2(sA); accA += fa.x + fa.y;
            float2 fb = __half22float2(sB); accB += fb.x + fb.y;
        }

        float ga = tanh_f(accA);   // lo: tanh(i)  hi: tanh(f)
        float gb = tanh_f(accB);   // lo: tanh(g)  hi: tanh(o)

        if (!hi) gsh[j] = sig_f(ga) * tanh_f(gb);   // u
        __syncthreads();

        if (hi) {
            c = c * sig_f(ga) + gsh[j];
            float hn = sig_f(gb) * tanh_f(c);

            float ho = __shfl_xor_sync(0xffffffffu, hn, 1);
            if (!(j & 1)) {
                __half2 hp = __floats2half2_rn(hn, ho);
                int k2 = half * 64 + (j >> 1);
                uint32_t off = (uint32_t)(((p ^ 1) * 128 + k2) * 4);
                hs2[(p ^ 1) * 128 + k2] = hp;                    // local copy
                if (t + 1 < TT) {                                // peer copy + signal
                    asm volatile("st.shared::cluster.u32 [%0], %1;"
                                 :: "r"(rHsBase + off), "r"(*(uint32_t*)&hp) : "memory");
                    uint32_t rm = ((t + 1) & 1) ? rMbar1 : rMbar0;
                    asm volatile("mbarrier.arrive.release.cluster.shared::cluster.b64 _, [%0];"
                                 :: "r"(rm) : "memory");
                }
            }
            out[((size_t)(b * HID + half * 128 + j)) * TT + t] = hn;
        }
        __syncthreads();

        wxA = nxA; wxB = nxB;
    }

    if (hi)
        out[(size_t)BB * HID * TT + b * HID + half * 128 + j] = c;

    asm volatile("barrier.cluster.arrive.aligned;\n\t"
                 "barrier.cluster.wait.aligned;" ::: "memory");
}

// ---------------- launch ------------------------------------------------------
extern "C" void kernel_launch(void* const* d_in, const int* in_sizes, int n_in,
                              void* d_out, int out_size) {
    const float* x   = (const float*)d_in[0];
    const float* h0  = (const float*)d_in[1];
    const float* c0  = (const float*)d_in[2];
    const float* Wih = (const float*)d_in[3];
    const float* Whh = (const float*)d_in[4];
    const float* bh  = (const float*)d_in[5];
    float* out = (float*)d_out;

    cudaFuncSetAttribute(lstm_rec_kernel,
                         cudaFuncAttributeMaxDynamicSharedMemorySize, SMEM_TOTAL_R);

    conv_whh_kernel<<<(BB * 2 * 16 * 512) / 256, 256>>>(Whh);

    wx_hmma_kernel<<<dim3(TT / 128, G4 / 128, BB), 256>>>(x, Wih, bh);

    lstm_rec_kernel<<<2 * BB, 256, SMEM_TOTAL_R>>>(h0, c0, out);

    (void)in_sizes; (void)n_in; (void)out_size;
}

// round 9
// speedup vs baseline: 1.0454x; 1.0454x over previous
#include <cuda_runtime.h>
#include <cuda_fp16.h>
#include <cstdint>
#include <math.h>

#define BB   64
#define CIN  256
#define HID  256
#define TT   512
#define G4   1024   // 4*HID

// ---------------- scratch (__device__ globals) ------------------------------
__device__ float g_wx[(size_t)TT * BB * G4];      // [t][b][col]  128 MiB
__device__ uint4 g_wA[(size_t)BB * 2 * 16 * 512]; // own-k block
__device__ uint4 g_wB[(size_t)BB * 2 * 16 * 512]; // peer-k block

// column slot lc in [0,512) -> global gate column.
// th = lc&255: unit j = th>>1, role = th&1 (0:(i,g), 1:(f,o)); sel = lc>>8.
// gate = sel*2 + role  ->  colB = colA + 512 preserved.
__device__ __forceinline__ int gcol(int lc, int half) {
    int th   = lc & 255;
    int sel  = lc >> 8;
    int role = th & 1;
    int j    = th >> 1;
    int g    = sel * 2 + role;
    return g * 256 + half * 128 + j;
}

__device__ __forceinline__ float tanh_f(float x) {
    float e = __expf(2.0f * x);
    return 1.0f - __fdividef(2.0f, e + 1.0f);
}
__device__ __forceinline__ float sig_f(float x) {
    return __fdividef(1.0f, 1.0f + __expf(-x));
}

// ---------------- conv: W_hh fp32 -> fp16 blobs ------------------------------
__global__ __launch_bounds__(256) void conv_whh_kernel(const float* __restrict__ Whh) {
    int t    = blockIdx.x * 256 + threadIdx.x;
    int lc   = t & 511;
    int k8   = (t >> 9) & 15;
    int half = (t >> 13) & 1;
    int b    = t >> 14;
    int col  = gcol(lc, half);
    {
        int kg0 = half * 128 + k8 * 8;
        const float* s = Whh + ((size_t)b * HID + kg0) * G4 + col;
        __half hx[8];
        #pragma unroll
        for (int i = 0; i < 8; i++) hx[i] = __float2half(s[(size_t)i * G4]);
        g_wA[t] = *(uint4*)hx;
    }
    {
        int kg0 = (1 - half) * 128 + k8 * 8;
        const float* s = Whh + ((size_t)b * HID + kg0) * G4 + col;
        __half hx[8];
        #pragma unroll
        for (int i = 0; i < 8; i++) hx[i] = __float2half(s[(size_t)i * G4]);
        g_wB[t] = *(uint4*)hx;
    }
}

// ---------------- phase 1: HMMA GEMM, double-buffered staging ---------------
__device__ __forceinline__ void mma16816(float* d, const uint32_t* a, const uint32_t* bf) {
    asm volatile(
        "mma.sync.aligned.m16n8k16.row.col.f32.f16.f16.f32 "
        "{%0,%1,%2,%3}, {%4,%5,%6,%7}, {%8,%9}, {%0,%1,%2,%3};"
        : "+f"(d[0]), "+f"(d[1]), "+f"(d[2]), "+f"(d[3])
        : "r"(a[0]), "r"(a[1]), "r"(a[2]), "r"(a[3]), "r"(bf[0]), "r"(bf[1]));
}

#define LDA 40

__global__ __launch_bounds__(256) void wx_hmma_kernel(
    const float* __restrict__ x,
    const float* __restrict__ Wih,
    const float* __restrict__ bh)
{
    __shared__ __half As[2][128 * LDA];
    __shared__ __half Bs[2][128 * LDA];

    const int tid  = threadIdx.x;
    const int m0   = blockIdx.x * 128;
    const int n0   = blockIdx.y * 128;
    const int b    = blockIdx.z;
    const int wid  = tid >> 5, lane = tid & 31;
    const int wm   = (wid & 1) * 64, wn = (wid >> 1) * 32;
    const int g    = lane >> 2, tig = lane & 3;

    float acc[4][4][4];
    #pragma unroll
    for (int i = 0; i < 4; i++)
        #pragma unroll
        for (int j = 0; j < 4; j++)
            #pragma unroll
            for (int r = 0; r < 4; r++) acc[i][j][r] = 0.0f;

    const float* xb = x   + (size_t)b * CIN * TT + m0;
    const float* wb = Wih + (size_t)b * CIN * G4 + n0;

    // staging indices (constant per thread)
    const int skl = tid >> 3;          // not used; keep layout identical to R6 loader
    (void)skl;

    // loader: stage 32k x 128 tile pair into buffer s
    auto load_stage = [&](int kb, int s) {
        #pragma unroll
        for (int i = 0; i < 4; i++) {
            int idx = tid + i * 256;
            int kl = idx >> 5, tq = idx & 31;
            float4 v = *(const float4*)(xb + (size_t)(kb + kl) * TT + tq * 4);
            __half* d = As[s] + (tq * 4) * LDA + kl;
            d[0]       = __float2half_rn(v.x);
            d[LDA]     = __float2half_rn(v.y);
            d[2 * LDA] = __float2half_rn(v.z);
            d[3 * LDA] = __float2half_rn(v.w);
        }
        #pragma unroll
        for (int i = 0; i < 4; i++) {
            int idx = tid + i * 256;
            int kl = idx >> 5, nq = idx & 31;
            float4 v = *(const float4*)(wb + (size_t)(kb + kl) * G4 + nq * 4);
            __half* d = Bs[s] + (nq * 4) * LDA + kl;
            d[0]       = __float2half_rn(v.x);
            d[LDA]     = __float2half_rn(v.y);
            d[2 * LDA] = __float2half_rn(v.z);
            d[3 * LDA] = __float2half_rn(v.w);
        }
    };

    load_stage(0, 0);
    __syncthreads();

    #pragma unroll 1
    for (int it = 0; it < 8; it++) {
        const int s = it & 1;
        if (it < 7) load_stage((it + 1) * 32, s ^ 1);   // overlap with mma below

        #pragma unroll
        for (int ks = 0; ks < 2; ks++) {
            uint32_t a[4][4], bf[4][2];
            #pragma unroll
            for (int mf = 0; mf < 4; mf++) {
                const __half* base = As[s] + (wm + mf * 16 + g) * LDA + ks * 16 + tig * 2;
                a[mf][0] = *(const uint32_t*)(base);
                a[mf][1] = *(const uint32_t*)(base + 8 * LDA);
                a[mf][2] = *(const uint32_t*)(base + 8);
                a[mf][3] = *(const uint32_t*)(base + 8 * LDA + 8);
            }
            #pragma unroll
            for (int nf = 0; nf < 4; nf++) {
                const __half* base = Bs[s] + (wn + nf * 8 + g) * LDA + ks * 16 + tig * 2;
                bf[nf][0] = *(const uint32_t*)(base);
                bf[nf][1] = *(const uint32_t*)(base + 8);
            }
            #pragma unroll
            for (int mf = 0; mf < 4; mf++)
                #pragma unroll
                for (int nf = 0; nf < 4; nf++)
                    mma16816(acc[mf][nf], a[mf], bf[nf]);
        }
        __syncthreads();
    }

    #pragma unroll
    for (int nf = 0; nf < 4; nf++) {
        int col = n0 + wn + nf * 8 + tig * 2;
        float2 bias = *(const float2*)(bh + (size_t)b * G4 + col);
        #pragma unroll
        for (int mf = 0; mf < 4; mf++) {
            int t0 = m0 + wm + mf * 16 + g;
            float2 v0 = { acc[mf][nf][0] + bias.x, acc[mf][nf][1] + bias.y };
            float2 v1 = { acc[mf][nf][2] + bias.x, acc[mf][nf][3] + bias.y };
            *(float2*)(g_wx + ((size_t)t0 * BB + b) * G4 + col) = v0;
            *(float2*)(g_wx + ((size_t)(t0 + 8) * BB + b) * G4 + col) = v1;
        }
    }
}

// ---------------- phase 2: recurrence, warp-local gate pairing --------------
#define SMEM_W_BYTES  (8 * 512 * 16)                  // 65536
#define SMEM_HS_OFF   SMEM_W_BYTES
#define SMEM_TOTAL_R  (SMEM_HS_OFF + 2 * 128 * 4)     // 66560 B

__global__ void __cluster_dims__(2, 1, 1) __launch_bounds__(256, 1)
lstm_rec_kernel(const float* __restrict__ h0,
                const float* __restrict__ c0,
                float* __restrict__ out)
{
    extern __shared__ char smem[];
    uint4*   w_s  = (uint4*)smem;                     // peer chunks 8..15
    __half2* hs2  = (__half2*)(smem + SMEM_HS_OFF);

    const int tid    = threadIdx.x;
    const int b      = blockIdx.x >> 1;
    const int half   = blockIdx.x & 1;
    const int HALF16 = half * 16;
    const int PEER16 = 16 - HALF16;
    const int role   = tid & 1;       // 0:(i,g)  1:(f,o)
    const int j      = tid >> 1;      // unit index (local)

    // weight residency (identical structure to R7; conv uses same gcol)
    uint4 wregA[16], wregB[16], wregPA[8], wregPB[8];
    const uint4* gwa = g_wA + ((size_t)(b * 2 + half) << 13);
    #pragma unroll
    for (int a = 0; a < 16; a++) {
        wregA[a] = gwa[a * 512 + tid];
        wregB[a] = gwa[a * 512 + tid + 256];
    }
    const uint4* gwb = g_wB + ((size_t)(b * 2 + half) << 13);
    #pragma unroll
    for (int a = 0; a < 8; a++) {
        wregPA[a] = gwb[a * 512 + tid];
        wregPB[a] = gwb[a * 512 + tid + 256];
    }
    #pragma unroll
    for (int a = 8; a < 16; a++) {
        w_s[(a - 8) * 512 + tid]       = gwb[a * 512 + tid];
        w_s[(a - 8) * 512 + tid + 256] = gwb[a * 512 + tid + 256];
    }

    // init state
    float c = 0.0f;
    if (role) c = c0[b * HID + half * 128 + j];
    if (tid < 128)
        hs2[tid] = __floats2half2_rn(h0[b * HID + 2 * tid],
                                     h0[b * HID + 2 * tid + 1]);
    __syncthreads();
    asm volatile("barrier.cluster.arrive.aligned;\n\t"
                 "barrier.cluster.wait.aligned;" ::: "memory");

    const uint32_t hsAddrBase = (uint32_t)__cvta_generic_to_shared(hs2);
    const uint32_t peerRank   = (uint32_t)(half ^ 1);
    uint32_t rHsBase;
    asm volatile("mapa.shared::cluster.u32 %0, %1, %2;"
                 : "=r"(rHsBase) : "r"(hsAddrBase), "r"(peerRank));

    const int colA = gcol(tid, half);
    const float* wxA_ptr = g_wx + (size_t)b * G4 + colA;
    const float* wxB_ptr = wxA_ptr + 512;

    float wxA = __ldg(wxA_ptr);
    float wxB = __ldg(wxB_ptr);
    const __half2 hz = __float2half2_rn(0.0f);

    #pragma unroll 1
    for (int t = 0; t < TT; t++) {
        const int p = t & 1;

        float nxA = wxA, nxB = wxB;
        if (t + 1 < TT) {
            size_t off = (size_t)(t + 1) * (BB * G4);
            nxA = __ldg(wxA_ptr + off);
            nxB = __ldg(wxB_ptr + off);
        }

        float accA = wxA, accB = wxB;
        const __half2* hsp = hs2 + p * 128;

        // ---- phase A: own-k block (register weights, local h) ----
        #pragma unroll
        for (int q = 0; q < 4; q++) {
            __half2 sA = hz, sB = hz;
            #pragma unroll
            for (int i = 0; i < 4; i++) {
                int a  = q * 4 + i;
                int k8 = HALF16 + a;
                uint4 hv = *(const uint4*)(hsp + k8 * 4);
                __half2 h01 = *(__half2*)&hv.x, h23 = *(__half2*)&hv.y;
                __half2 h45 = *(__half2*)&hv.z, h67 = *(__half2*)&hv.w;
                uint4 wa = wregA[a], wb = wregB[a];
                sA = __hfma2(h01, *(__half2*)&wa.x, sA);
                sA = __hfma2(h23, *(__half2*)&wa.y, sA);
                sA = __hfma2(h45, *(__half2*)&wa.z, sA);
                sA = __hfma2(h67, *(__half2*)&wa.w, sA);
                sB = __hfma2(h01, *(__half2*)&wb.x, sB);
                sB = __hfma2(h23, *(__half2*)&wb.y, sB);
                sB = __hfma2(h45, *(__half2*)&wb.z, sB);
                sB = __hfma2(h67, *(__half2*)&wb.w, sB);
            }
            float2 fa = __half22float2(sA); accA += fa.x + fa.y;
            float2 fb = __half22float2(sB); accB += fb.x + fb.y;
        }

        // ---- wait for peer h of this step (split cluster barrier) ----
        if (t) asm volatile("barrier.cluster.wait.aligned;" ::: "memory");

        // ---- phase B: peer-k block (8 reg chunks + 8 SMEM chunks) ----
        #pragma unroll
        for (int q = 0; q < 4; q++) {
            __half2 sA = hz, sB = hz;
            #pragma unroll
            for (int i = 0; i < 4; i++) {
                int bi = q * 4 + i;
                int k8 = PEER16 + bi;
                uint4 hv = *(const uint4*)(hsp + k8 * 4);
                __half2 h01 = *(__half2*)&hv.x, h23 = *(__half2*)&hv.y;
                __half2 h45 = *(__half2*)&hv.z, h67 = *(__half2*)&hv.w;
                uint4 wa, wb;
                if (bi < 8) { wa = wregPA[bi]; wb = wregPB[bi]; }
                else {
                    wa = w_s[(bi - 8) * 512 + tid];
                    wb = w_s[(bi - 8) * 512 + tid + 256];
                }
                sA = __hfma2(h01, *(__half2*)&wa.x, sA);
                sA = __hfma2(h23, *(__half2*)&wa.y, sA);
                sA = __hfma2(h45, *(__half2*)&wa.z, sA);
                sA = __hfma2(h67, *(__half2*)&wa.w, sA);
                sB = __hfma2(h01, *(__half2*)&wb.x, sB);
                sB = __hfma2(h23, *(__half2*)&wb.y, sB);
                sB = __hfma2(h45, *(__half2*)&wb.z, sB);
                sB = __hfma2(h67, *(__half2*)&wb.w, sB);
            }
            float2 fa = __half22float2(sA); accA += fa.x + fa.y;
            float2 fb = __half22float2(sB); accB += fb.x + fb.y;
        }

        // ---- activations: role 0 -> (i,g), role 1 -> (f,o) ----
        float ga  = tanh_f(accA);
        float gb  = tanh_f(accB);
        float sga = sig_f(ga);            // role0: sigma(i)  role1: sigma(f)

        float u = 0.0f;
        if (!role) u = sga * tanh_f(gb);  // u = sigma(i)*tanh(g)
        float ux = __shfl_xor_sync(0xffffffffu, u, 1);   // odd gets even's u

        float hn = 0.0f;
        if (role) {
            float so = sig_f(gb);         // sigma(o)
            c = c * sga + ux;
            hn = so * tanh_f(c);
            out[((size_t)(b * HID + half * 128 + j)) * TT + t] = hn;
        }

        // pack neighbor-unit h: odd tids hold hn; tid%4==1 packs (j, j+1)
        float ho = __shfl_xor_sync(0xffffffffu, hn, 2);
        if (role && !(j & 1)) {
            __half2 hp = __floats2half2_rn(hn, ho);
            int k2 = half * 64 + (j >> 1);
            uint32_t off = (uint32_t)(((p ^ 1) * 128 + k2) * 4);
            hs2[(p ^ 1) * 128 + k2] = hp;                    // local copy
            if (t + 1 < TT)
                asm volatile("st.shared::cluster.u32 [%0], %1;"
                             :: "r"(rHsBase + off), "r"(*(uint32_t*)&hp) : "memory");
        }
        __syncthreads();
        asm volatile("barrier.cluster.arrive.aligned;" ::: "memory");

        wxA = nxA; wxB = nxB;
    }
    asm volatile("barrier.cluster.wait.aligned;" ::: "memory");

    if (role)
        out[(size_t)BB * HID * TT + b * HID + half * 128 + j] = c;
}

// ---------------- launch ------------------------------------------------------
extern "C" void kernel_launch(void* const* d_in, const int* in_sizes, int n_in,
                              void* d_out, int out_size) {
    const float* x   = (const float*)d_in[0];
    const float* h0  = (const float*)d_in[1];
    const float* c0  = (const float*)d_in[2];
    const float* Wih = (const float*)d_in[3];
    const float* Whh = (const float*)d_in[4];
    const float* bh  = (const float*)d_in[5];
    float* out = (float*)d_out;

    cudaFuncSetAttribute(lstm_rec_kernel,
                         cudaFuncAttributeMaxDynamicSharedMemorySize, SMEM_TOTAL_R);

    conv_whh_kernel<<<(BB * 2 * 16 * 512) / 256, 256>>>(Whh);

    wx_hmma_kernel<<<dim3(TT / 128, G4 / 128, BB), 256>>>(x, Wih, bh);

    lstm_rec_kernel<<<2 * BB, 256, SMEM_TOTAL_R>>>(h0, c0, out);

    (void)in_sizes; (void)n_in; (void)out_size;
}

// round 10
// speedup vs baseline: 1.2010x; 1.1489x over previous
#include <cuda_runtime.h>
#include <cuda_fp16.h>
#include <cstdint>
#include <math.h>

#define BB   64
#define CIN  256
#define HID  256
#define TT   512
#define G4   1024   // 4*HID

// ---------------- scratch (__device__ globals) ------------------------------
__device__ float g_wx[(size_t)TT * BB * G4];      // [t][b][col]  128 MiB
__device__ uint4 g_wA[(size_t)BB * 2 * 16 * 512]; // own-k block
__device__ uint4 g_wB[(size_t)BB * 2 * 16 * 512]; // peer-k block

// column slot lc in [0,512) -> global gate column.
// th = lc&255: unit j = th>>1, role = th&1 (0:(i,g), 1:(f,o)); sel = lc>>8.
// gate = sel*2 + role  ->  colB = colA + 512 preserved.
__device__ __forceinline__ int gcol(int lc, int half) {
    int th   = lc & 255;
    int sel  = lc >> 8;
    int role = th & 1;
    int j    = th >> 1;
    int g    = sel * 2 + role;
    return g * 256 + half * 128 + j;
}

__device__ __forceinline__ float tanh_f(float x) {
    float e = __expf(2.0f * x);
    return 1.0f - __fdividef(2.0f, e + 1.0f);
}
__device__ __forceinline__ float sig_f(float x) {
    return __fdividef(1.0f, 1.0f + __expf(-x));
}

// ---------------- conv: W_hh fp32 -> fp16 blobs ------------------------------
__global__ __launch_bounds__(256) void conv_whh_kernel(const float* __restrict__ Whh) {
    int t    = blockIdx.x * 256 + threadIdx.x;
    int lc   = t & 511;
    int k8   = (t >> 9) & 15;
    int half = (t >> 13) & 1;
    int b    = t >> 14;
    int col  = gcol(lc, half);
    {
        int kg0 = half * 128 + k8 * 8;
        const float* s = Whh + ((size_t)b * HID + kg0) * G4 + col;
        __half hx[8];
        #pragma unroll
        for (int i = 0; i < 8; i++) hx[i] = __float2half(s[(size_t)i * G4]);
        g_wA[t] = *(uint4*)hx;
    }
    {
        int kg0 = (1 - half) * 128 + k8 * 8;
        const float* s = Whh + ((size_t)b * HID + kg0) * G4 + col;
        __half hx[8];
        #pragma unroll
        for (int i = 0; i < 8; i++) hx[i] = __float2half(s[(size_t)i * G4]);
        g_wB[t] = *(uint4*)hx;
    }
}

// ---------------- phase 1: single-kernel HMMA GEMM (R6/R7-proven) -----------
__device__ __forceinline__ void mma16816(float* d, const uint32_t* a, const uint32_t* bf) {
    asm volatile(
        "mma.sync.aligned.m16n8k16.row.col.f32.f16.f16.f32 "
        "{%0,%1,%2,%3}, {%4,%5,%6,%7}, {%8,%9}, {%0,%1,%2,%3};"
        : "+f"(d[0]), "+f"(d[1]), "+f"(d[2]), "+f"(d[3])
        : "r"(a[0]), "r"(a[1]), "r"(a[2]), "r"(a[3]), "r"(bf[0]), "r"(bf[1]));
}

#define LDA 40

__global__ __launch_bounds__(256) void wx_hmma_kernel(
    const float* __restrict__ x,
    const float* __restrict__ Wih,
    const float* __restrict__ bh)
{
    __shared__ __half As[128 * LDA];
    __shared__ __half Bs[128 * LDA];

    const int tid  = threadIdx.x;
    const int m0   = blockIdx.x * 128;
    const int n0   = blockIdx.y * 128;
    const int b    = blockIdx.z;
    const int wid  = tid >> 5, lane = tid & 31;
    const int wm   = (wid & 1) * 64, wn = (wid >> 1) * 32;
    const int g    = lane >> 2, tig = lane & 3;

    float acc[4][4][4];
    #pragma unroll
    for (int i = 0; i < 4; i++)
        #pragma unroll
        for (int j = 0; j < 4; j++)
            #pragma unroll
            for (int r = 0; r < 4; r++) acc[i][j][r] = 0.0f;

    const float* xb = x   + (size_t)b * CIN * TT + m0;
    const float* wb = Wih + (size_t)b * CIN * G4 + n0;

    #pragma unroll 1
    for (int kb = 0; kb < CIN; kb += 32) {
        #pragma unroll
        for (int i = 0; i < 4; i++) {
            int idx = tid + i * 256;
            int kl = idx >> 5, tq = idx & 31;
            float4 v = *(const float4*)(xb + (size_t)(kb + kl) * TT + tq * 4);
            __half* d = As + (tq * 4) * LDA + kl;
            d[0]       = __float2half_rn(v.x);
            d[LDA]     = __float2half_rn(v.y);
            d[2 * LDA] = __float2half_rn(v.z);
            d[3 * LDA] = __float2half_rn(v.w);
        }
        #pragma unroll
        for (int i = 0; i < 4; i++) {
            int idx = tid + i * 256;
            int kl = idx >> 5, nq = idx & 31;
            float4 v = *(const float4*)(wb + (size_t)(kb + kl) * G4 + nq * 4);
            __half* d = Bs + (nq * 4) * LDA + kl;
            d[0]       = __float2half_rn(v.x);
            d[LDA]     = __float2half_rn(v.y);
            d[2 * LDA] = __float2half_rn(v.z);
            d[3 * LDA] = __float2half_rn(v.w);
        }
        __syncthreads();

        #pragma unroll
        for (int ks = 0; ks < 2; ks++) {
            uint32_t a[4][4], bf[4][2];
            #pragma unroll
            for (int mf = 0; mf < 4; mf++) {
                const __half* base = As + (wm + mf * 16 + g) * LDA + ks * 16 + tig * 2;
                a[mf][0] = *(const uint32_t*)(base);
                a[mf][1] = *(const uint32_t*)(base + 8 * LDA);
                a[mf][2] = *(const uint32_t*)(base + 8);
                a[mf][3] = *(const uint32_t*)(base + 8 * LDA + 8);
            }
            #pragma unroll
            for (int nf = 0; nf < 4; nf++) {
                const __half* base = Bs + (wn + nf * 8 + g) * LDA + ks * 16 + tig * 2;
                bf[nf][0] = *(const uint32_t*)(base);
                bf[nf][1] = *(const uint32_t*)(base + 8);
            }
            #pragma unroll
            for (int mf = 0; mf < 4; mf++)
                #pragma unroll
                for (int nf = 0; nf < 4; nf++)
                    mma16816(acc[mf][nf], a[mf], bf[nf]);
        }
        __syncthreads();
    }

    #pragma unroll
    for (int nf = 0; nf < 4; nf++) {
        int col = n0 + wn + nf * 8 + tig * 2;
        float2 bias = *(const float2*)(bh + (size_t)b * G4 + col);
        #pragma unroll
        for (int mf = 0; mf < 4; mf++) {
            int t0 = m0 + wm + mf * 16 + g;
            float2 v0 = { acc[mf][nf][0] + bias.x, acc[mf][nf][1] + bias.y };
            float2 v1 = { acc[mf][nf][2] + bias.x, acc[mf][nf][3] + bias.y };
            *(float2*)(g_wx + ((size_t)t0 * BB + b) * G4 + col) = v0;
            *(float2*)(g_wx + ((size_t)(t0 + 8) * BB + b) * G4 + col) = v1;
        }
    }
}

// ---------------- phase 2: recurrence, redundant branch-free tail -----------
#define SMEM_W_BYTES  (8 * 512 * 16)                  // 65536
#define SMEM_HS_OFF   SMEM_W_BYTES
#define SMEM_TOTAL_R  (SMEM_HS_OFF + 2 * 128 * 4)     // 66560 B

__global__ void __cluster_dims__(2, 1, 1) __launch_bounds__(256, 1)
lstm_rec_kernel(const float* __restrict__ h0,
                const float* __restrict__ c0,
                float* __restrict__ out)
{
    extern __shared__ char smem[];
    uint4*   w_s  = (uint4*)smem;                     // peer chunks 8..15
    __half2* hs2  = (__half2*)(smem + SMEM_HS_OFF);

    const int tid    = threadIdx.x;
    const int b      = blockIdx.x >> 1;
    const int half   = blockIdx.x & 1;
    const int HALF16 = half * 16;
    const int PEER16 = 16 - HALF16;
    const int role   = tid & 1;       // 0:(i,g)  1:(f,o)
    const int j      = tid >> 1;      // unit index (local, 0..127)

    // weight residency (R7 structure)
    uint4 wregA[16], wregB[16], wregPA[8], wregPB[8];
    const uint4* gwa = g_wA + ((size_t)(b * 2 + half) << 13);
    #pragma unroll
    for (int a = 0; a < 16; a++) {
        wregA[a] = gwa[a * 512 + tid];
        wregB[a] = gwa[a * 512 + tid + 256];
    }
    const uint4* gwb = g_wB + ((size_t)(b * 2 + half) << 13);
    #pragma unroll
    for (int a = 0; a < 8; a++) {
        wregPA[a] = gwb[a * 512 + tid];
        wregPB[a] = gwb[a * 512 + tid + 256];
    }
    #pragma unroll
    for (int a = 8; a < 16; a++) {
        w_s[(a - 8) * 512 + tid]       = gwb[a * 512 + tid];
        w_s[(a - 8) * 512 + tid + 256] = gwb[a * 512 + tid + 256];
    }

    // init state: BOTH threads of a pair hold c redundantly
    float c = c0[b * HID + half * 128 + j];
    if (tid < 128)
        hs2[tid] = __floats2half2_rn(h0[b * HID + 2 * tid],
                                     h0[b * HID + 2 * tid + 1]);
    __syncthreads();
    asm volatile("barrier.cluster.arrive.aligned;\n\t"
                 "barrier.cluster.wait.aligned;" ::: "memory");

    const uint32_t hsAddrBase = (uint32_t)__cvta_generic_to_shared(hs2);
    const uint32_t peerRank   = (uint32_t)(half ^ 1);
    uint32_t rHsBase;
    asm volatile("mapa.shared::cluster.u32 %0, %1, %2;"
                 : "=r"(rHsBase) : "r"(hsAddrBase), "r"(peerRank));

    const int colA = gcol(tid, half);
    const float* wxA_ptr = g_wx + (size_t)b * G4 + colA;
    const float* wxB_ptr = wxA_ptr + 512;

    float wxA = __ldg(wxA_ptr);
    float wxB = __ldg(wxB_ptr);
    const __half2 hz = __float2half2_rn(0.0f);

    #pragma unroll 1
    for (int t = 0; t < TT; t++) {
        const int p = t & 1;

        float nxA = wxA, nxB = wxB;
        if (t + 1 < TT) {
            size_t off = (size_t)(t + 1) * (BB * G4);
            nxA = __ldg(wxA_ptr + off);
            nxB = __ldg(wxB_ptr + off);
        }

        float accA = wxA, accB = wxB;
        const __half2* hsp = hs2 + p * 128;

        // ---- phase A: own-k block (register weights, local h) ----
        #pragma unroll
        for (int q = 0; q < 4; q++) {
            __half2 sA = hz, sB = hz;
            #pragma unroll
            for (int i = 0; i < 4; i++) {
                int a  = q * 4 + i;
                int k8 = HALF16 + a;
                uint4 hv = *(const uint4*)(hsp + k8 * 4);
                __half2 h01 = *(__half2*)&hv.x, h23 = *(__half2*)&hv.y;
                __half2 h45 = *(__half2*)&hv.z, h67 = *(__half2*)&hv.w;
                uint4 wa = wregA[a], wb = wregB[a];
                sA = __hfma2(h01, *(__half2*)&wa.x, sA);
                sA = __hfma2(h23, *(__half2*)&wa.y, sA);
                sA = __hfma2(h45, *(__half2*)&wa.z, sA);
                sA = __hfma2(h67, *(__half2*)&wa.w, sA);
                sB = __hfma2(h01, *(__half2*)&wb.x, sB);
                sB = __hfma2(h23, *(__half2*)&wb.y, sB);
                sB = __hfma2(h45, *(__half2*)&wb.z, sB);
                sB = __hfma2(h67, *(__half2*)&wb.w, sB);
            }
            float2 fa = __half22float2(sA); accA += fa.x + fa.y;
            float2 fb = __half22float2(sB); accB += fb.x + fb.y;
        }

        // ---- wait for peer h of this step (split cluster barrier) ----
        if (t) asm volatile("barrier.cluster.wait.aligned;" ::: "memory");

        // ---- phase B: peer-k block (8 reg chunks + 8 SMEM chunks) ----
        #pragma unroll
        for (int q = 0; q < 4; q++) {
            __half2 sA = hz, sB = hz;
            #pragma unroll
            for (int i = 0; i < 4; i++) {
                int bi = q * 4 + i;
                int k8 = PEER16 + bi;
                uint4 hv = *(const uint4*)(hsp + k8 * 4);
                __half2 h01 = *(__half2*)&hv.x, h23 = *(__half2*)&hv.y;
                __half2 h45 = *(__half2*)&hv.z, h67 = *(__half2*)&hv.w;
                uint4 wa, wb;
                if (bi < 8) { wa = wregPA[bi]; wb = wregPB[bi]; }
                else {
                    wa = w_s[(bi - 8) * 512 + tid];
                    wb = w_s[(bi - 8) * 512 + tid + 256];
                }
                sA = __hfma2(h01, *(__half2*)&wa.x, sA);
                sA = __hfma2(h23, *(__half2*)&wa.y, sA);
                sA = __hfma2(h45, *(__half2*)&wa.z, sA);
                sA = __hfma2(h67, *(__half2*)&wa.w, sA);
                sB = __hfma2(h01, *(__half2*)&wb.x, sB);
                sB = __hfma2(h23, *(__half2*)&wb.y, sB);
                sB = __hfma2(h45, *(__half2*)&wb.z, sB);
                sB = __hfma2(h67, *(__half2*)&wb.w, sB);
            }
            float2 fa = __half22float2(sA); accA += fa.x + fa.y;
            float2 fb = __half22float2(sB); accB += fb.x + fb.y;
        }

        // ---- branch-free redundant activation tail ----
        float ga = tanh_f(accA);   // role0: tanh(i)   role1: tanh(f)
        float gb = tanh_f(accB);   // role0: tanh(g)   role1: tanh(o)
        float gax = __shfl_xor_sync(0xffffffffu, ga, 1);
        float gbx = __shfl_xor_sync(0xffffffffu, gb, 1);

        float ti = role ? gax : ga;
        float tf = role ? ga  : gax;
        float tg = role ? gbx : gb;
        float to = role ? gb  : gbx;

        c = c * sig_f(tf) + sig_f(ti) * tanh_f(tg);
        float hn = sig_f(to) * tanh_f(c);

        if (role)
            out[((size_t)(b * HID + half * 128 + j)) * TT + t] = hn;

        // pack h pair: tid%4==0 packs units (j, j+1); hn(j+1) lives at tid+2
        float ho = __shfl_xor_sync(0xffffffffu, hn, 2);
        if ((tid & 3) == 0) {
            __half2 hp = __floats2half2_rn(hn, ho);
            int k2 = half * 64 + (tid >> 2);
            uint32_t off = (uint32_t)(((p ^ 1) * 128 + k2) * 4);
            hs2[(p ^ 1) * 128 + k2] = hp;                    // local copy
            if (t + 1 < TT)
                asm volatile("st.shared::cluster.u32 [%0], %1;"
                             :: "r"(rHsBase + off), "r"(*(uint32_t*)&hp) : "memory");
        }
        __syncthreads();
        asm volatile("barrier.cluster.arrive.aligned;" ::: "memory");

        wxA = nxA; wxB = nxB;
    }
    asm volatile("barrier.cluster.wait.aligned;" ::: "memory");

    if (role)
        out[(size_t)BB * HID * TT + b * HID + half * 128 + j] = c;
}

// ---------------- launch ------------------------------------------------------
extern "C" void kernel_launch(void* const* d_in, const int* in_sizes, int n_in,
                              void* d_out, int out_size) {
    const float* x   = (const float*)d_in[0];
    const float* h0  = (const float*)d_in[1];
    const float* c0  = (const float*)d_in[2];
    const float* Wih = (const float*)d_in[3];
    const float* Whh = (const float*)d_in[4];
    const float* bh  = (const float*)d_in[5];
    float* out = (float*)d_out;

    cudaFuncSetAttribute(lstm_rec_kernel,
                         cudaFuncAttributeMaxDynamicSharedMemorySize, SMEM_TOTAL_R);

    conv_whh_kernel<<<(BB * 2 * 16 * 512) / 256, 256>>>(Whh);

    wx_hmma_kernel<<<dim3(TT / 128, G4 / 128, BB), 256>>>(x, Wih, bh);

    lstm_rec_kernel<<<2 * BB, 256, SMEM_TOTAL_R>>>(h0, c0, out);

    (void)in_sizes; (void)n_in; (void)out_size;
}